// round 13
// baseline (speedup 1.0000x reference)
#include <cuda_runtime.h>
#include <cuda_bf16.h>
#include <math.h>
#include <float.h>
#include <stdint.h>

// Problem constants
#define S    2048
#define D    4096         // H*HD
#define HQ   32           // query heads
#define G    8            // kv heads
#define HD   128
#define E    6144         // D + 2*G*HD
#define HG   4            // HQ / G
#define EPSF 1e-5f

typedef __nv_bfloat16 bf16;
typedef __nv_bfloat162 bf162;

// ---------------------------------------------------------------------------
// Scratch (device globals; no runtime allocation allowed)
// ---------------------------------------------------------------------------
__device__ float g_qkv[(size_t)S * E];
__device__ float g_scores[(size_t)HQ * S * S];
__device__ float g_cos[(size_t)S * (HD / 2)];
__device__ float g_sin[(size_t)S * (HD / 2)];

__device__ bf16 g_xh[(size_t)S * D],        g_xl[(size_t)S * D];
__device__ bf16 g_wqh[(size_t)E * D],       g_wql[(size_t)E * D];
__device__ bf16 g_woh[(size_t)D * D],       g_wol[(size_t)D * D];
__device__ bf16 g_qh[(size_t)S * D],        g_ql[(size_t)S * D];
__device__ bf16 g_kh[(size_t)S * G * HD],   g_kl[(size_t)S * G * HD];
__device__ bf16 g_vth[(size_t)G * HD * S],  g_vtl[(size_t)G * HD * S];
__device__ bf16 g_ph[(size_t)HQ * S * S],   g_pl[(size_t)HQ * S * S];
__device__ bf16 g_ah[(size_t)S * D],        g_al[(size_t)S * D];

// ---------------------------------------------------------------------------
// Helpers
// ---------------------------------------------------------------------------
__device__ __forceinline__ uint32_t smem_u32_of(const void* p) {
    uint32_t a;
    asm("{ .reg .u64 t; cvta.to.shared.u64 t, %1; cvt.u32.u64 %0, t; }" : "=r"(a) : "l"(p));
    return a;
}

#define CP_ASYNC16(dst, src) \
    asm volatile("cp.async.cg.shared.global [%0], [%1], 16;" :: "r"(dst), "l"(src))
#define CP_COMMIT()  asm volatile("cp.async.commit_group;" ::: "memory")

#define LDMAT_X4(r0, r1, r2, r3, a) \
    asm volatile("ldmatrix.sync.aligned.m8n8.x4.shared.b16 {%0,%1,%2,%3}, [%4];" \
        : "=r"(r0), "=r"(r1), "=r"(r2), "=r"(r3) : "r"(a))

#define MMA16816(d, a, b0v, b1v) \
    asm volatile("mma.sync.aligned.m16n8k16.row.col.f32.bf16.bf16.f32 " \
        "{%0,%1,%2,%3}, {%4,%5,%6,%7}, {%8,%9}, {%0,%1,%2,%3};" \
        : "+f"((d)[0]), "+f"((d)[1]), "+f"((d)[2]), "+f"((d)[3]) \
        : "r"((a)[0]), "r"((a)[1]), "r"((a)[2]), "r"((a)[3]), "r"(b0v), "r"(b1v))

__device__ __forceinline__ void split1(float v, bf16& h, bf16& l) {
    h = __float2bfloat16(v);
    l = __float2bfloat16(v - __bfloat162float(h));
}

// ---------------------------------------------------------------------------
// Warp-MMA bf16x3 GEMM, merged planes, K-chunk 64, occupancy 1:
//   C[M,N] = alpha * (Ah*Bh + Al*Bh + Ah*Bl)[M,K]x[N,K]^T   (fp32 accum)
// Per k-chunk (64 deep) all four tiles (Ah,Al,Bh,Bl) loaded once; 192 MMAs
// between barriers (half the barrier count of kc32). Occupancy 1 frees the
// register budget (no __launch_bounds__ min-blocks -> ptxas up to 255 regs,
// no spills). Block tile 128x128x64, 256 thr (8 warps 2x4), warp tile 64x32.
// 2-stage cp.async double buffer; 144B smem row stride (conflict-free:
// successive rows land on distinct 16B banks, 144 mod 128 = 16*r).
//   CAUSAL 0: none | 1: skip tile if n0>=m0+128 (QK) | 2: K<=m0+128 (PV)
//   SPLITOUT 0: fp32 C | 1: bf16 hi/lo C pair
// Per-z offsets; B z-index = z / bzdiv (GQA).
// ---------------------------------------------------------------------------
#define KC      64                   // K-chunk depth
#define RS      144                  // smem row stride bytes (64 bf16 + 16B pad)
#define TILE_B  (128 * RS)           // 18432 bytes per operand tile
#define STAGE_B (4 * TILE_B)         // Ah + Al + Bh + Bl per stage = 73728
#define NSTG    2

__device__ __forceinline__ void load_tile_async(uint32_t sdst, const bf16* src,
                                                int ld, int tid) {
    #pragma unroll
    for (int it = 0; it < 4; it++) {
        int idx = tid + it * 256;
        int row = idx >> 3, ch = idx & 7;     // 8 x 16B chunks per 128B row
        const bf16* g = src + (long long)row * ld + ch * 8;
        CP_ASYNC16(sdst + row * RS + ch * 16, g);
    }
}

template <int CAUSAL, int SPLITOUT>
__global__ void __launch_bounds__(256)
mma_gemm(const bf16* __restrict__ Ah, const bf16* __restrict__ Al,
         const bf16* __restrict__ Bh, const bf16* __restrict__ Bl,
         float* __restrict__ C, bf16* __restrict__ Ch, bf16* __restrict__ Cl,
         int K, int lda, int ldb, int ldc,
         long long sAz, long long sBz, long long sCz, int bzdiv, float alpha) {
    int m0 = blockIdx.y * 128;
    int n0 = blockIdx.x * 128;
    if (CAUSAL == 1 && n0 >= m0 + 128) return;

    int z = blockIdx.z;
    const bf16* AhZ = Ah + (long long)z * sAz + (long long)m0 * lda;
    const bf16* AlZ = Al + (long long)z * sAz + (long long)m0 * lda;
    const bf16* BhZ = Bh + (long long)(z / bzdiv) * sBz + (long long)n0 * ldb;
    const bf16* BlZ = Bl + (long long)(z / bzdiv) * sBz + (long long)n0 * ldb;

    int Keff = (CAUSAL == 2) ? ((K < m0 + 128) ? K : (m0 + 128)) : K;
    int NT   = Keff / KC;            // k-chunks of 64 (all Keff here are multiples)

    extern __shared__ __align__(16) char smem[];     // NSTG * STAGE_B
    uint32_t smb = smem_u32_of(smem);

    int tid  = threadIdx.x;
    int warp = tid >> 5, lane = tid & 31;
    int wm = (warp >> 2) * 64;       // warp row offset (2 warps in m)
    int wn = (warp & 3) * 32;        // warp col offset (4 warps in n)

    float acc[4][4][4];
    #pragma unroll
    for (int i = 0; i < 4; i++)
        #pragma unroll
        for (int j = 0; j < 4; j++)
            #pragma unroll
            for (int t = 0; t < 4; t++) acc[i][j][t] = 0.0f;

    // per-lane ldmatrix base offsets (within one operand tile)
    uint32_t aLane = (uint32_t)((wm + (lane & 15)) * RS + (lane >> 4) * 16);
    uint32_t bLane = (uint32_t)((wn + ((lane >> 4) << 3) + (lane & 7)) * RS
                                + ((lane >> 3) & 1) * 16);

    auto load_stage = [&](int kc, uint32_t sb) {
        load_tile_async(sb,              AhZ + kc * KC, lda, tid);
        load_tile_async(sb + TILE_B,     AlZ + kc * KC, lda, tid);
        load_tile_async(sb + 2 * TILE_B, BhZ + kc * KC, ldb, tid);
        load_tile_async(sb + 3 * TILE_B, BlZ + kc * KC, ldb, tid);
    };

    // prologue: stage 0
    load_stage(0, smb);
    CP_COMMIT();

    for (int i = 0; i < NT; i++) {
        if (i + 1 < NT) {
            load_stage(i + 1, smb + ((i + 1) & 1) * STAGE_B);
            CP_COMMIT();
            asm volatile("cp.async.wait_group 1;" ::: "memory");
        } else {
            asm volatile("cp.async.wait_group 0;" ::: "memory");
        }
        __syncthreads();

        uint32_t sb  = smb + (i & 1) * STAGE_B;
        uint32_t aHA = sb + aLane;
        uint32_t aLA = sb + TILE_B + aLane;
        uint32_t bHA = sb + 2 * TILE_B + bLane;
        uint32_t bLA = sb + 3 * TILE_B + bLane;

        #pragma unroll
        for (int kk = 0; kk < KC / 16; kk++) {     // four k16 steps per chunk
            uint32_t bh[2][4], bl[2][4];
            #pragma unroll
            for (int nb2 = 0; nb2 < 2; nb2++) {
                LDMAT_X4(bh[nb2][0], bh[nb2][1], bh[nb2][2], bh[nb2][3],
                         bHA + nb2 * (16 * RS) + kk * 32);
                LDMAT_X4(bl[nb2][0], bl[nb2][1], bl[nb2][2], bl[nb2][3],
                         bLA + nb2 * (16 * RS) + kk * 32);
            }
            #pragma unroll
            for (int mp = 0; mp < 2; mp++) {       // ma-pairs {0,1},{2,3}
                uint32_t ah[2][4], al[2][4];
                #pragma unroll
                for (int mi = 0; mi < 2; mi++) {
                    int ma = mp * 2 + mi;
                    LDMAT_X4(ah[mi][0], ah[mi][1], ah[mi][2], ah[mi][3],
                             aHA + ma * (16 * RS) + kk * 32);
                    LDMAT_X4(al[mi][0], al[mi][1], al[mi][2], al[mi][3],
                             aLA + ma * (16 * RS) + kk * 32);
                }
                // plane 0: ah x bh
                #pragma unroll
                for (int mi = 0; mi < 2; mi++)
                    #pragma unroll
                    for (int nb2 = 0; nb2 < 2; nb2++) {
                        MMA16816(acc[mp * 2 + mi][nb2 * 2 + 0], ah[mi], bh[nb2][0], bh[nb2][1]);
                        MMA16816(acc[mp * 2 + mi][nb2 * 2 + 1], ah[mi], bh[nb2][2], bh[nb2][3]);
                    }
                // plane 1: al x bh
                #pragma unroll
                for (int mi = 0; mi < 2; mi++)
                    #pragma unroll
                    for (int nb2 = 0; nb2 < 2; nb2++) {
                        MMA16816(acc[mp * 2 + mi][nb2 * 2 + 0], al[mi], bh[nb2][0], bh[nb2][1]);
                        MMA16816(acc[mp * 2 + mi][nb2 * 2 + 1], al[mi], bh[nb2][2], bh[nb2][3]);
                    }
                // plane 2: ah x bl
                #pragma unroll
                for (int mi = 0; mi < 2; mi++)
                    #pragma unroll
                    for (int nb2 = 0; nb2 < 2; nb2++) {
                        MMA16816(acc[mp * 2 + mi][nb2 * 2 + 0], ah[mi], bl[nb2][0], bl[nb2][1]);
                        MMA16816(acc[mp * 2 + mi][nb2 * 2 + 1], ah[mi], bl[nb2][2], bl[nb2][3]);
                    }
            }
        }
        __syncthreads();   // protect this slot from next iteration's cp.async
    }

    // epilogue
    int group = lane >> 2, tig = lane & 3;
    #pragma unroll
    for (int ma = 0; ma < 4; ma++) {
        int r0 = m0 + wm + ma * 16 + group;
        #pragma unroll
        for (int na = 0; na < 4; na++) {
            int c = n0 + wn + na * 8 + tig * 2;
            #pragma unroll
            for (int half = 0; half < 2; half++) {
                long long off = (long long)(r0 + half * 8) * ldc + c
                              + (long long)z * sCz;
                float v0 = acc[ma][na][half * 2 + 0] * alpha;
                float v1 = acc[ma][na][half * 2 + 1] * alpha;
                if (SPLITOUT) {
                    bf16 h0, l0, h1, l1;
                    split1(v0, h0, l0); split1(v1, h1, l1);
                    *(bf162*)(Ch + off) = bf162(h0, h1);
                    *(bf162*)(Cl + off) = bf162(l0, l1);
                } else {
                    *(float2*)(C + off) = make_float2(v0, v1);
                }
            }
        }
    }
}

// ---------------------------------------------------------------------------
// fp32 -> bf16 hi/lo split (2D strided source, contiguous dest)
// ---------------------------------------------------------------------------
__global__ void split_kernel(const float* __restrict__ src, int ldsrc, int cols,
                             bf16* __restrict__ hi, bf16* __restrict__ lo,
                             long long total) {
    long long i4 = ((long long)blockIdx.x * blockDim.x + threadIdx.x) * 4;
    if (i4 >= total) return;
    long long r = i4 / cols;
    int c = (int)(i4 - r * cols);
    float4 v = *(const float4*)(src + r * (long long)ldsrc + c);
    bf16 h0, l0, h1, l1, h2, l2, h3, l3;
    split1(v.x, h0, l0); split1(v.y, h1, l1);
    split1(v.z, h2, l2); split1(v.w, h3, l3);
    *(bf162*)(hi + i4)     = bf162(h0, h1);
    *(bf162*)(hi + i4 + 2) = bf162(h2, h3);
    *(bf162*)(lo + i4)     = bf162(l0, l1);
    *(bf162*)(lo + i4 + 2) = bf162(l2, l3);
}

// V transpose + split via smem tiles (coalesced both sides).
// Source: qkv[t][D + G*HD + c], c in [0,1024). Dest: vt[c][t], [1024][S].
__global__ void vsplit_kernel(const float* __restrict__ qkv,
                              bf16* __restrict__ vth, bf16* __restrict__ vtl) {
    __shared__ float tile[32][33];
    int tbase = blockIdx.x * 32;       // t tile
    int cbase = blockIdx.y * 32;       // c tile
    int tx = threadIdx.x, ty = threadIdx.y;   // 32 x 8
    #pragma unroll
    for (int j = 0; j < 4; j++) {
        int row = ty + j * 8;          // t offset
        tile[row][tx] = qkv[(long long)(tbase + row) * E + D + G * HD + cbase + tx];
    }
    __syncthreads();
    #pragma unroll
    for (int j = 0; j < 4; j++) {
        int c = cbase + ty + j * 8;
        float v = tile[tx][ty + j * 8];
        bf16 h, l;
        split1(v, h, l);
        long long o = (long long)c * S + tbase + tx;
        vth[o] = h; vtl[o] = l;
    }
}

// ---------------------------------------------------------------------------
// RoPE cos/sin table (matches reference fp32 semantics)
// ---------------------------------------------------------------------------
__global__ void rope_table_kernel(float* __restrict__ cosT, float* __restrict__ sinT) {
    int idx = blockIdx.x * blockDim.x + threadIdx.x;
    if (idx >= S * (HD / 2)) return;
    int s = idx >> 6;
    int i = idx & 63;
    double freq_d = pow(1.0e6, -(double)(2 * i) / 128.0);
    float  ang = (float)s * (float)freq_d;
    double cd, sd;
    sincos((double)ang, &sd, &cd);
    cosT[idx] = (float)cd;
    sinT[idx] = (float)sd;
}

// ---------------------------------------------------------------------------
// Fused RMSNorm + RoPE + bf16 hi/lo split. Reads fp32 q/k from g_qkv,
// writes qh/ql (dense [S,D]) and kh/kl (dense [S,G*HD]). One warp per row.
// ---------------------------------------------------------------------------
__global__ void rmsnorm_rope_split_kernel(const float* __restrict__ qkv,
                                          const float* __restrict__ qw,
                                          const float* __restrict__ kw,
                                          const float* __restrict__ cosT,
                                          const float* __restrict__ sinT,
                                          bf16* __restrict__ qh, bf16* __restrict__ ql,
                                          bf16* __restrict__ kh, bf16* __restrict__ kl) {
    int gwarp = (blockIdx.x * blockDim.x + threadIdx.x) >> 5;
    int lane  = threadIdx.x & 31;
    const int NROWS = S * (HQ + G);
    if (gwarp >= NROWS) return;
    int s  = gwarp / (HQ + G);
    int hh = gwarp % (HQ + G);

    const float* row;
    const float* w;
    bf16 *dh, *dl;
    if (hh < HQ) {
        row = qkv + (long long)s * E + hh * HD;            w = qw;
        dh = qh + (long long)s * D + hh * HD;
        dl = ql + (long long)s * D + hh * HD;
    } else {
        row = qkv + (long long)s * E + D + (hh - HQ) * HD; w = kw;
        dh = kh + (long long)s * (G * HD) + (hh - HQ) * HD;
        dl = kl + (long long)s * (G * HD) + (hh - HQ) * HD;
    }

    const float2* row2 = (const float2*)row;
    float2 a = row2[lane], b = row2[lane + 32];
    float ss = a.x * a.x + a.y * a.y + b.x * b.x + b.y * b.y;
    #pragma unroll
    for (int o = 16; o; o >>= 1) ss += __shfl_xor_sync(0xFFFFFFFFu, ss, o);
    float r = rsqrtf(ss * (1.0f / 128.0f) + EPSF);

    const float2* w2 = (const float2*)w;
    float2 wa = w2[lane], wb = w2[lane + 32];
    float ax = (a.x * r) * wa.x, ay = (a.y * r) * wa.y;
    float bx = (b.x * r) * wb.x, by = (b.y * r) * wb.y;

    int base = s * (HD / 2);
    float c0 = cosT[base + lane],      s0 = sinT[base + lane];
    float c1 = cosT[base + lane + 32], s1 = sinT[base + lane + 32];

    float o0 = ax * c0 - ay * s0, o1 = ax * s0 + ay * c0;
    float o2 = bx * c1 - by * s1, o3 = bx * s1 + by * c1;

    bf16 h0, l0, h1, l1, h2, l2, h3, l3;
    split1(o0, h0, l0); split1(o1, h1, l1);
    split1(o2, h2, l2); split1(o3, h3, l3);
    ((bf162*)dh)[lane]      = bf162(h0, h1);
    ((bf162*)dl)[lane]      = bf162(l0, l1);
    ((bf162*)dh)[lane + 32] = bf162(h2, h3);
    ((bf162*)dl)[lane + 32] = bf162(l2, l3);
}

// ---------------------------------------------------------------------------
// Causal softmax reading fp32 scores, writing bf16 hi/lo probs.
// Zero-fills up to ceil128(s+1) (exactly the slack the K-limited PV reads).
// ---------------------------------------------------------------------------
__global__ void softmax_split_kernel(const float* __restrict__ scores,
                                     bf16* __restrict__ ph, bf16* __restrict__ pl) {
    int s = blockIdx.x, h = blockIdx.y;
    const float* row = scores + ((long long)h * S + s) * (long long)S;
    bf16* phr = ph + ((long long)h * S + s) * (long long)S;
    bf16* plr = pl + ((long long)h * S + s) * (long long)S;
    int n = s + 1;
    int nend = (n + 127) & ~127;
    int tid = threadIdx.x;

    float v[8];
    float mx = -FLT_MAX;
    #pragma unroll
    for (int i = 0; i < 8; i++) {
        int t = tid + i * 256;
        v[i] = (t < n) ? row[t] : -FLT_MAX;
        mx = fmaxf(mx, v[i]);
    }
    __shared__ float red[8];
    #pragma unroll
    for (int o = 16; o; o >>= 1) mx = fmaxf(mx, __shfl_xor_sync(0xFFFFFFFFu, mx, o));
    if ((tid & 31) == 0) red[tid >> 5] = mx;
    __syncthreads();
    mx = red[0];
    #pragma unroll
    for (int w = 1; w < 8; w++) mx = fmaxf(mx, red[w]);
    __syncthreads();

    float sum = 0.0f;
    #pragma unroll
    for (int i = 0; i < 8; i++) {
        int t = tid + i * 256;
        v[i] = (t < n) ? expf(v[i] - mx) : 0.0f;
        sum += v[i];
    }
    #pragma unroll
    for (int o = 16; o; o >>= 1) sum += __shfl_xor_sync(0xFFFFFFFFu, sum, o);
    if ((tid & 31) == 0) red[tid >> 5] = sum;
    __syncthreads();
    float tot = red[0];
    #pragma unroll
    for (int w = 1; w < 8; w++) tot += red[w];
    float inv = 1.0f / tot;

    #pragma unroll
    for (int i = 0; i < 8; i++) {
        int t = tid + i * 256;
        if (t < nend) {
            float pv = (t < n) ? v[i] * inv : 0.0f;
            bf16 hh, ll;
            split1(pv, hh, ll);
            phr[t] = hh; plr[t] = ll;
        }
    }
}

// ---------------------------------------------------------------------------
// Launch
// ---------------------------------------------------------------------------
extern "C" void kernel_launch(void* const* d_in, const int* in_sizes, int n_in,
                              void* d_out, int out_size) {
    const float* x     = (const float*)d_in[0];
    const float* w_qkv = (const float*)d_in[1];
    const float* w_out = (const float*)d_in[2];
    const float* qw    = (const float*)d_in[3];
    const float* kw    = (const float*)d_in[4];
    float* out = (float*)d_out;

    float *qkv, *scores, *cosT, *sinT;
    cudaGetSymbolAddress((void**)&qkv,    g_qkv);
    cudaGetSymbolAddress((void**)&scores, g_scores);
    cudaGetSymbolAddress((void**)&cosT,   g_cos);
    cudaGetSymbolAddress((void**)&sinT,   g_sin);
    bf16 *xh,*xl,*wqh,*wql,*woh,*wol,*qh,*ql,*kh,*kl,*vth,*vtl,*ph,*pl,*ah,*al;
    cudaGetSymbolAddress((void**)&xh,  g_xh);  cudaGetSymbolAddress((void**)&xl,  g_xl);
    cudaGetSymbolAddress((void**)&wqh, g_wqh); cudaGetSymbolAddress((void**)&wql, g_wql);
    cudaGetSymbolAddress((void**)&woh, g_woh); cudaGetSymbolAddress((void**)&wol, g_wol);
    cudaGetSymbolAddress((void**)&qh,  g_qh);  cudaGetSymbolAddress((void**)&ql,  g_ql);
    cudaGetSymbolAddress((void**)&kh,  g_kh);  cudaGetSymbolAddress((void**)&kl,  g_kl);
    cudaGetSymbolAddress((void**)&vth, g_vth); cudaGetSymbolAddress((void**)&vtl, g_vtl);
    cudaGetSymbolAddress((void**)&ph,  g_ph);  cudaGetSymbolAddress((void**)&pl,  g_pl);
    cudaGetSymbolAddress((void**)&ah,  g_ah);  cudaGetSymbolAddress((void**)&al,  g_al);

    const int SMEM = NSTG * STAGE_B;   // 147456
    cudaFuncSetAttribute(mma_gemm<0, 0>, cudaFuncAttributeMaxDynamicSharedMemorySize, SMEM);
    cudaFuncSetAttribute(mma_gemm<1, 0>, cudaFuncAttributeMaxDynamicSharedMemorySize, SMEM);
    cudaFuncSetAttribute(mma_gemm<2, 1>, cudaFuncAttributeMaxDynamicSharedMemorySize, SMEM);

    const float scale = 0.08838834764831845f;   // 1/sqrt(128)

    // #0 RoPE tables
    rope_table_kernel<<<(S * (HD / 2) + 255) / 256, 256>>>(cosT, sinT);

    // #1, #2: splits for QKV GEMM inputs
    {
        long long tx = (long long)S * D;
        split_kernel<<<(unsigned)((tx / 4 + 255) / 256), 256>>>(x, D, D, xh, xl, tx);
        long long tw = (long long)E * D;
        split_kernel<<<(unsigned)((tw / 4 + 255) / 256), 256>>>(w_qkv, D, D, wqh, wql, tw);
    }

    // #3 QKV projection: qkv = x @ w_qkv^T
    {
        dim3 grid(E / 128, S / 128, 1);
        mma_gemm<0, 0><<<grid, 256, SMEM>>>(xh, xl, wqh, wql, qkv, nullptr, nullptr,
                                            D, D, D, E, 0, 0, 0, 1, 1.0f);
    }

    // #4 RMSNorm + RoPE + split -> qh/ql, kh/kl
    rmsnorm_rope_split_kernel<<<S * (HQ + G) / 8, 256>>>(qkv, qw, kw, cosT, sinT,
                                                         qh, ql, kh, kl);

    // #5 scores[h] = scale * Q_h @ K_{h/4}^T  (causal tile skip)  [ncu target]
    {
        dim3 grid(S / 128, S / 128, HQ);
        mma_gemm<1, 0><<<grid, 256, SMEM>>>(qh, ql, kh, kl, scores, nullptr, nullptr,
                                            HD, D, G * HD, S,
                                            HD, HD, (long long)S * S, HG, scale);
    }

    // #6 V transpose + split (smem tiled, coalesced)
    {
        dim3 vg(S / 32, (G * HD) / 32);
        vsplit_kernel<<<vg, dim3(32, 8)>>>(qkv, vth, vtl);
    }

    // #7 causal softmax -> bf16 hi/lo probs
    {
        dim3 grid(S, HQ);
        softmax_split_kernel<<<grid, 256>>>(scores, ph, pl);
    }

    // #8 attn cols h*128.. = P_h @ V_{h/4}^T  (K-limited), emits ah/al bf16
    {
        dim3 grid(1, S / 128, HQ);
        mma_gemm<2, 1><<<grid, 256, SMEM>>>(ph, pl, vth, vtl, nullptr, ah, al,
                                            S, S, S, D,
                                            (long long)S * S, (long long)HD * S, HD, HG, 1.0f);
    }

    // #9 split w_out (independent; placed late so QK GEMM is launch #5)
    {
        long long to = (long long)D * D;
        split_kernel<<<(unsigned)((to / 4 + 255) / 256), 256>>>(w_out, D, D, woh, wol, to);
    }

    // #10 out = attn @ w_out^T
    {
        dim3 grid(D / 128, S / 128, 1);
        mma_gemm<0, 0><<<grid, 256, SMEM>>>(ah, al, woh, wol, out, nullptr, nullptr,
                                            D, D, D, D, 0, 0, 0, 1, 1.0f);
    }
}

// round 15
// speedup vs baseline: 1.1200x; 1.1200x over previous
#include <cuda_runtime.h>
#include <cuda_bf16.h>
#include <math.h>
#include <float.h>
#include <stdint.h>

// Problem constants
#define S    2048
#define D    4096         // H*HD
#define HQ   32           // query heads
#define G    8            // kv heads
#define HD   128
#define E    6144         // D + 2*G*HD
#define HG   4            // HQ / G
#define EPSF 1e-5f

typedef __nv_bfloat16 bf16;
typedef __nv_bfloat162 bf162;

// ---------------------------------------------------------------------------
// Scratch (device globals; no runtime allocation allowed)
// ---------------------------------------------------------------------------
__device__ float g_qkv[(size_t)S * E];
__device__ float g_cos[(size_t)S * (HD / 2)];
__device__ float g_sin[(size_t)S * (HD / 2)];

__device__ bf16 g_xh[(size_t)S * D],        g_xl[(size_t)S * D];
__device__ bf16 g_wqh[(size_t)E * D],       g_wql[(size_t)E * D];
__device__ bf16 g_woh[(size_t)D * D],       g_wol[(size_t)D * D];
__device__ bf16 g_qh[(size_t)S * D],        g_ql[(size_t)S * D];
__device__ bf16 g_kh[(size_t)S * G * HD],   g_kl[(size_t)S * G * HD];
__device__ bf16 g_vth[(size_t)G * HD * S],  g_vtl[(size_t)G * HD * S];
__device__ bf16 g_ah[(size_t)S * D],        g_al[(size_t)S * D];

// ---------------------------------------------------------------------------
// Helpers
// ---------------------------------------------------------------------------
__device__ __forceinline__ uint32_t smem_u32_of(const void* p) {
    uint32_t a;
    asm("{ .reg .u64 t; cvta.to.shared.u64 t, %1; cvt.u32.u64 %0, t; }" : "=r"(a) : "l"(p));
    return a;
}

#define CP_ASYNC16(dst, src) \
    asm volatile("cp.async.cg.shared.global [%0], [%1], 16;" :: "r"(dst), "l"(src))
#define CP_COMMIT()  asm volatile("cp.async.commit_group;" ::: "memory")

#define LDMAT_X4(r0, r1, r2, r3, a) \
    asm volatile("ldmatrix.sync.aligned.m8n8.x4.shared.b16 {%0,%1,%2,%3}, [%4];" \
        : "=r"(r0), "=r"(r1), "=r"(r2), "=r"(r3) : "r"(a))

#define MMA16816(d, a, b0v, b1v) \
    asm volatile("mma.sync.aligned.m16n8k16.row.col.f32.bf16.bf16.f32 " \
        "{%0,%1,%2,%3}, {%4,%5,%6,%7}, {%8,%9}, {%0,%1,%2,%3};" \
        : "+f"((d)[0]), "+f"((d)[1]), "+f"((d)[2]), "+f"((d)[3]) \
        : "r"((a)[0]), "r"((a)[1]), "r"((a)[2]), "r"((a)[3]), "r"(b0v), "r"(b1v))

__device__ __forceinline__ void split1(float v, bf16& h, bf16& l) {
    h = __float2bfloat16(v);
    l = __float2bfloat16(v - __bfloat162float(h));
}

// pack two floats into bf16 hi-pair and lo-pair registers (low half = first)
__device__ __forceinline__ void pack2(float a, float b, uint32_t& hi, uint32_t& lo) {
    bf16 ha, la, hb, lb;
    split1(a, ha, la); split1(b, hb, lb);
    bf162 H(ha, hb), L(la, lb);
    hi = *(uint32_t*)&H; lo = *(uint32_t*)&L;
}

// ---------------------------------------------------------------------------
// Warp-MMA bf16x3 GEMM (projections): C = A[M,K] * B[N,K]^T  (fp32 accum)
// Merged planes (Ah*Bh + Al*Bh + Ah*Bl) per k-chunk of 32; tile 128x128,
// 256 thr (8 warps 2x4), warp tile 64x32; 2-stage cp.async; 80B row stride.
// ---------------------------------------------------------------------------
#define RS      80
#define TILE_B  (128 * RS)
#define STAGE_B (4 * TILE_B)         // 40960
#define NSTG    2

__device__ __forceinline__ void load_tile_async(uint32_t sdst, const bf16* src,
                                                int ld, int tid) {
    #pragma unroll
    for (int it = 0; it < 2; it++) {
        int idx = tid + it * 256;
        int row = idx >> 2, ch = idx & 3;
        const bf16* g = src + (long long)row * ld + ch * 8;
        CP_ASYNC16(sdst + row * RS + ch * 16, g);
    }
}

__global__ void __launch_bounds__(256, 2)
mma_gemm(const bf16* __restrict__ Ah, const bf16* __restrict__ Al,
         const bf16* __restrict__ Bh, const bf16* __restrict__ Bl,
         float* __restrict__ C, int K, int lda, int ldb, int ldc) {
    int m0 = blockIdx.y * 128;
    int n0 = blockIdx.x * 128;

    const bf16* AhZ = Ah + (long long)m0 * lda;
    const bf16* AlZ = Al + (long long)m0 * lda;
    const bf16* BhZ = Bh + (long long)n0 * ldb;
    const bf16* BlZ = Bl + (long long)n0 * ldb;

    int NT = K >> 5;

    extern __shared__ __align__(16) char smem[];
    uint32_t smb = smem_u32_of(smem);

    int tid  = threadIdx.x;
    int warp = tid >> 5, lane = tid & 31;
    int wm = (warp >> 2) * 64;
    int wn = (warp & 3) * 32;

    float acc[4][4][4];
    #pragma unroll
    for (int i = 0; i < 4; i++)
        #pragma unroll
        for (int j = 0; j < 4; j++)
            #pragma unroll
            for (int t = 0; t < 4; t++) acc[i][j][t] = 0.0f;

    uint32_t aLane = (uint32_t)((wm + (lane & 15)) * RS + (lane >> 4) * 16);
    uint32_t bLane = (uint32_t)((wn + ((lane >> 4) << 3) + (lane & 7)) * RS
                                + ((lane >> 3) & 1) * 16);

    auto load_stage = [&](int kc, uint32_t sb) {
        load_tile_async(sb,              AhZ + kc * 32, lda, tid);
        load_tile_async(sb + TILE_B,     AlZ + kc * 32, lda, tid);
        load_tile_async(sb + 2 * TILE_B, BhZ + kc * 32, ldb, tid);
        load_tile_async(sb + 3 * TILE_B, BlZ + kc * 32, ldb, tid);
    };

    load_stage(0, smb);
    CP_COMMIT();

    for (int i = 0; i < NT; i++) {
        if (i + 1 < NT) {
            load_stage(i + 1, smb + ((i + 1) & 1) * STAGE_B);
            CP_COMMIT();
            asm volatile("cp.async.wait_group 1;" ::: "memory");
        } else {
            asm volatile("cp.async.wait_group 0;" ::: "memory");
        }
        __syncthreads();

        uint32_t sb  = smb + (i & 1) * STAGE_B;
        uint32_t aHA = sb + aLane;
        uint32_t aLA = sb + TILE_B + aLane;
        uint32_t bHA = sb + 2 * TILE_B + bLane;
        uint32_t bLA = sb + 3 * TILE_B + bLane;

        #pragma unroll
        for (int kk = 0; kk < 2; kk++) {
            uint32_t bh[2][4], bl[2][4];
            #pragma unroll
            for (int nb2 = 0; nb2 < 2; nb2++) {
                LDMAT_X4(bh[nb2][0], bh[nb2][1], bh[nb2][2], bh[nb2][3],
                         bHA + nb2 * (16 * RS) + kk * 32);
                LDMAT_X4(bl[nb2][0], bl[nb2][1], bl[nb2][2], bl[nb2][3],
                         bLA + nb2 * (16 * RS) + kk * 32);
            }
            #pragma unroll
            for (int mp = 0; mp < 2; mp++) {
                uint32_t ah[2][4], al[2][4];
                #pragma unroll
                for (int mi = 0; mi < 2; mi++) {
                    int ma = mp * 2 + mi;
                    LDMAT_X4(ah[mi][0], ah[mi][1], ah[mi][2], ah[mi][3],
                             aHA + ma * (16 * RS) + kk * 32);
                    LDMAT_X4(al[mi][0], al[mi][1], al[mi][2], al[mi][3],
                             aLA + ma * (16 * RS) + kk * 32);
                }
                #pragma unroll
                for (int mi = 0; mi < 2; mi++)
                    #pragma unroll
                    for (int nb2 = 0; nb2 < 2; nb2++) {
                        MMA16816(acc[mp * 2 + mi][nb2 * 2 + 0], ah[mi], bh[nb2][0], bh[nb2][1]);
                        MMA16816(acc[mp * 2 + mi][nb2 * 2 + 1], ah[mi], bh[nb2][2], bh[nb2][3]);
                    }
                #pragma unroll
                for (int mi = 0; mi < 2; mi++)
                    #pragma unroll
                    for (int nb2 = 0; nb2 < 2; nb2++) {
                        MMA16816(acc[mp * 2 + mi][nb2 * 2 + 0], al[mi], bh[nb2][0], bh[nb2][1]);
                        MMA16816(acc[mp * 2 + mi][nb2 * 2 + 1], al[mi], bh[nb2][2], bh[nb2][3]);
                    }
                #pragma unroll
                for (int mi = 0; mi < 2; mi++)
                    #pragma unroll
                    for (int nb2 = 0; nb2 < 2; nb2++) {
                        MMA16816(acc[mp * 2 + mi][nb2 * 2 + 0], ah[mi], bl[nb2][0], bl[nb2][1]);
                        MMA16816(acc[mp * 2 + mi][nb2 * 2 + 1], ah[mi], bl[nb2][2], bl[nb2][3]);
                    }
            }
        }
        __syncthreads();
    }

    int group = lane >> 2, tig = lane & 3;
    #pragma unroll
    for (int ma = 0; ma < 4; ma++) {
        int r0 = m0 + wm + ma * 16 + group;
        #pragma unroll
        for (int na = 0; na < 4; na++) {
            int c = n0 + wn + na * 8 + tig * 2;
            #pragma unroll
            for (int half = 0; half < 2; half++) {
                long long off = (long long)(r0 + half * 8) * ldc + c;
                *(float2*)(C + off) = make_float2(acc[ma][na][half * 2 + 0],
                                                  acc[ma][na][half * 2 + 1]);
            }
        }
    }
}

// ---------------------------------------------------------------------------
// Fused flash attention: per CTA = (q-block of 128 rows, one query head).
// Q tile resident in smem (hi/lo); loop kv tiles j<=qi: QK bf16x3 -> online
// softmax (log2 domain, quad-shfl row reductions) -> P hi/lo in registers ->
// PV bf16x3 into O accumulators. Writes ah/al bf16 hi/lo [S,D].
// 256 thr, warp w owns rows 16w..16w+15 (m16 x n128 per warp).
// ---------------------------------------------------------------------------
#define FRS   272                    // 256B row + 16B pad (odd 16B multiple)
#define FTILE (128 * FRS)            // 34816
#define FSMEM (6 * FTILE)            // 208896

__global__ void __launch_bounds__(256)
flash_kernel(const bf16* __restrict__ qh, const bf16* __restrict__ ql,
             const bf16* __restrict__ kh, const bf16* __restrict__ kl,
             const bf16* __restrict__ vth, const bf16* __restrict__ vtl,
             bf16* __restrict__ ah, bf16* __restrict__ al) {
    int qi = blockIdx.x;             // q block 0..15
    int h  = blockIdx.y;             // head 0..31
    int g  = h / HG;                 // kv head

    extern __shared__ __align__(16) char smem[];
    uint32_t smb = smem_u32_of(smem);
    uint32_t sQh = smb,             sQl = smb + FTILE;
    uint32_t sKh = smb + 2 * FTILE, sKl = smb + 3 * FTILE;
    uint32_t sVh = smb + 4 * FTILE, sVl = smb + 5 * FTILE;

    int tid = threadIdx.x, warp = tid >> 5, lane = tid & 31;

    // load Q tile once (128 rows x 256B, hi and lo)
    #pragma unroll
    for (int it = 0; it < 8; it++) {
        int idx = tid + it * 256;
        int row = idx >> 4, ch = idx & 15;
        long long go = (long long)(128 * qi + row) * D + h * 128 + ch * 8;
        CP_ASYNC16(sQh + row * FRS + ch * 16, qh + go);
        CP_ASYNC16(sQl + row * FRS + ch * 16, ql + go);
    }
    CP_COMMIT();

    uint32_t aOff = (uint32_t)((16 * warp + (lane & 15)) * FRS + (lane >> 4) * 16);
    uint32_t bOff = (uint32_t)((((lane >> 4) << 3) + (lane & 7)) * FRS
                               + ((lane >> 3) & 1) * 16);

    float o_acc[16][4];
    #pragma unroll
    for (int i = 0; i < 16; i++)
        #pragma unroll
        for (int t = 0; t < 4; t++) o_acc[i][t] = 0.0f;
    float mrow0 = -FLT_MAX, mrow1 = -FLT_MAX;
    float lrow0 = 0.0f,     lrow1 = 0.0f;

    const float SCL2 = 0.08838834764831845f * 1.4426950408889634f; // scale*log2e
    int r0g = 128 * qi + 16 * warp + (lane >> 2);

    for (int j = 0; j <= qi; j++) {
        __syncthreads();             // prior reads done before overwrite
        #pragma unroll
        for (int it = 0; it < 8; it++) {
            int idx = tid + it * 256;
            int row = idx >> 4, ch = idx & 15;
            long long gk = (long long)(128 * j + row) * (G * HD) + g * 128 + ch * 8;
            long long gv = (long long)(g * 128 + row) * S + 128 * j + ch * 8;
            CP_ASYNC16(sKh + row * FRS + ch * 16, kh + gk);
            CP_ASYNC16(sKl + row * FRS + ch * 16, kl + gk);
            CP_ASYNC16(sVh + row * FRS + ch * 16, vth + gv);
            CP_ASYNC16(sVl + row * FRS + ch * 16, vtl + gv);
        }
        CP_COMMIT();
        asm volatile("cp.async.wait_group 0;" ::: "memory");
        __syncthreads();

        // ---- QK^T (bf16x3) ----
        float s_acc[16][4];
        #pragma unroll
        for (int i2 = 0; i2 < 16; i2++)
            #pragma unroll
            for (int t = 0; t < 4; t++) s_acc[i2][t] = 0.0f;

        #pragma unroll
        for (int kk = 0; kk < 8; kk++) {
            uint32_t qhf[4], qlf[4];
            LDMAT_X4(qhf[0], qhf[1], qhf[2], qhf[3], sQh + aOff + kk * 32);
            LDMAT_X4(qlf[0], qlf[1], qlf[2], qlf[3], sQl + aOff + kk * 32);
            #pragma unroll
            for (int nt = 0; nt < 8; nt++) {
                uint32_t khf[4], klf[4];
                LDMAT_X4(khf[0], khf[1], khf[2], khf[3],
                         sKh + bOff + nt * (16 * FRS) + kk * 32);
                LDMAT_X4(klf[0], klf[1], klf[2], klf[3],
                         sKl + bOff + nt * (16 * FRS) + kk * 32);
                MMA16816(s_acc[2 * nt + 0], qhf, khf[0], khf[1]);
                MMA16816(s_acc[2 * nt + 1], qhf, khf[2], khf[3]);
                MMA16816(s_acc[2 * nt + 0], qlf, khf[0], khf[1]);
                MMA16816(s_acc[2 * nt + 1], qlf, khf[2], khf[3]);
                MMA16816(s_acc[2 * nt + 0], qhf, klf[0], klf[1]);
                MMA16816(s_acc[2 * nt + 1], qhf, klf[2], klf[3]);
            }
        }

        // ---- scale to log2 domain (+ causal mask on diagonal tile) ----
        if (j == qi) {
            #pragma unroll
            for (int nt = 0; nt < 16; nt++) {
                int col = 128 * j + nt * 8 + (lane & 3) * 2;
                s_acc[nt][0] = (col     <= r0g)     ? s_acc[nt][0] * SCL2 : -FLT_MAX;
                s_acc[nt][1] = (col + 1 <= r0g)     ? s_acc[nt][1] * SCL2 : -FLT_MAX;
                s_acc[nt][2] = (col     <= r0g + 8) ? s_acc[nt][2] * SCL2 : -FLT_MAX;
                s_acc[nt][3] = (col + 1 <= r0g + 8) ? s_acc[nt][3] * SCL2 : -FLT_MAX;
            }
        } else {
            #pragma unroll
            for (int nt = 0; nt < 16; nt++) {
                s_acc[nt][0] *= SCL2; s_acc[nt][1] *= SCL2;
                s_acc[nt][2] *= SCL2; s_acc[nt][3] *= SCL2;
            }
        }

        // ---- online softmax (rows live in 4-lane quads) ----
        float mt0 = -FLT_MAX, mt1 = -FLT_MAX;
        #pragma unroll
        for (int nt = 0; nt < 16; nt++) {
            mt0 = fmaxf(mt0, fmaxf(s_acc[nt][0], s_acc[nt][1]));
            mt1 = fmaxf(mt1, fmaxf(s_acc[nt][2], s_acc[nt][3]));
        }
        mt0 = fmaxf(mt0, __shfl_xor_sync(0xFFFFFFFFu, mt0, 1));
        mt0 = fmaxf(mt0, __shfl_xor_sync(0xFFFFFFFFu, mt0, 2));
        mt1 = fmaxf(mt1, __shfl_xor_sync(0xFFFFFFFFu, mt1, 1));
        mt1 = fmaxf(mt1, __shfl_xor_sync(0xFFFFFFFFu, mt1, 2));
        float m0 = fmaxf(mrow0, mt0), m1 = fmaxf(mrow1, mt1);
        float f0 = exp2f(mrow0 - m0), f1 = exp2f(mrow1 - m1);
        float sum0 = 0.0f, sum1 = 0.0f;
        #pragma unroll
        for (int nt = 0; nt < 16; nt++) {
            s_acc[nt][0] = exp2f(s_acc[nt][0] - m0);
            s_acc[nt][1] = exp2f(s_acc[nt][1] - m0);
            s_acc[nt][2] = exp2f(s_acc[nt][2] - m1);
            s_acc[nt][3] = exp2f(s_acc[nt][3] - m1);
            sum0 += s_acc[nt][0] + s_acc[nt][1];
            sum1 += s_acc[nt][2] + s_acc[nt][3];
        }
        sum0 += __shfl_xor_sync(0xFFFFFFFFu, sum0, 1);
        sum0 += __shfl_xor_sync(0xFFFFFFFFu, sum0, 2);
        sum1 += __shfl_xor_sync(0xFFFFFFFFu, sum1, 1);
        sum1 += __shfl_xor_sync(0xFFFFFFFFu, sum1, 2);
        lrow0 = lrow0 * f0 + sum0;  lrow1 = lrow1 * f1 + sum1;
        mrow0 = m0;                 mrow1 = m1;
        #pragma unroll
        for (int i2 = 0; i2 < 16; i2++) {
            o_acc[i2][0] *= f0; o_acc[i2][1] *= f0;
            o_acc[i2][2] *= f1; o_acc[i2][3] *= f1;
        }

        // ---- PV (bf16x3): C-frag of QK == A-frag of PV ----
        #pragma unroll
        for (int kk2 = 0; kk2 < 8; kk2++) {
            uint32_t pa[4], pb[4];
            pack2(s_acc[2 * kk2][0],     s_acc[2 * kk2][1],     pa[0], pb[0]);
            pack2(s_acc[2 * kk2][2],     s_acc[2 * kk2][3],     pa[1], pb[1]);
            pack2(s_acc[2 * kk2 + 1][0], s_acc[2 * kk2 + 1][1], pa[2], pb[2]);
            pack2(s_acc[2 * kk2 + 1][2], s_acc[2 * kk2 + 1][3], pa[3], pb[3]);
            #pragma unroll
            for (int ont = 0; ont < 8; ont++) {
                uint32_t vhf[4], vlf[4];
                LDMAT_X4(vhf[0], vhf[1], vhf[2], vhf[3],
                         sVh + bOff + ont * (16 * FRS) + kk2 * 32);
                LDMAT_X4(vlf[0], vlf[1], vlf[2], vlf[3],
                         sVl + bOff + ont * (16 * FRS) + kk2 * 32);
                MMA16816(o_acc[2 * ont + 0], pa, vhf[0], vhf[1]);
                MMA16816(o_acc[2 * ont + 1], pa, vhf[2], vhf[3]);
                MMA16816(o_acc[2 * ont + 0], pb, vhf[0], vhf[1]);
                MMA16816(o_acc[2 * ont + 1], pb, vhf[2], vhf[3]);
                MMA16816(o_acc[2 * ont + 0], pa, vlf[0], vlf[1]);
                MMA16816(o_acc[2 * ont + 1], pa, vlf[2], vlf[3]);
            }
        }
    }

    // ---- epilogue: normalize and emit bf16 hi/lo ----
    float inv0 = 1.0f / lrow0, inv1 = 1.0f / lrow1;
    #pragma unroll
    for (int ont = 0; ont < 16; ont++) {
        int col = h * 128 + ont * 8 + (lane & 3) * 2;
        long long off0 = (long long)r0g * D + col;
        long long off1 = (long long)(r0g + 8) * D + col;
        bf16 h0, l0, h1, l1;
        split1(o_acc[ont][0] * inv0, h0, l0);
        split1(o_acc[ont][1] * inv0, h1, l1);
        *(bf162*)(ah + off0) = bf162(h0, h1);
        *(bf162*)(al + off0) = bf162(l0, l1);
        split1(o_acc[ont][2] * inv1, h0, l0);
        split1(o_acc[ont][3] * inv1, h1, l1);
        *(bf162*)(ah + off1) = bf162(h0, h1);
        *(bf162*)(al + off1) = bf162(l0, l1);
    }
}

// ---------------------------------------------------------------------------
// fp32 -> bf16 hi/lo split (2D strided source, contiguous dest)
// ---------------------------------------------------------------------------
__global__ void split_kernel(const float* __restrict__ src, int ldsrc, int cols,
                             bf16* __restrict__ hi, bf16* __restrict__ lo,
                             long long total) {
    long long i4 = ((long long)blockIdx.x * blockDim.x + threadIdx.x) * 4;
    if (i4 >= total) return;
    long long r = i4 / cols;
    int c = (int)(i4 - r * cols);
    float4 v = *(const float4*)(src + r * (long long)ldsrc + c);
    bf16 h0, l0, h1, l1, h2, l2, h3, l3;
    split1(v.x, h0, l0); split1(v.y, h1, l1);
    split1(v.z, h2, l2); split1(v.w, h3, l3);
    *(bf162*)(hi + i4)     = bf162(h0, h1);
    *(bf162*)(hi + i4 + 2) = bf162(h2, h3);
    *(bf162*)(lo + i4)     = bf162(l0, l1);
    *(bf162*)(lo + i4 + 2) = bf162(l2, l3);
}

// ---------------------------------------------------------------------------
// RoPE cos/sin table (matches reference fp32 semantics)
// ---------------------------------------------------------------------------
__global__ void rope_table_kernel(float* __restrict__ cosT, float* __restrict__ sinT) {
    int idx = blockIdx.x * blockDim.x + threadIdx.x;
    if (idx >= S * (HD / 2)) return;
    int s = idx >> 6;
    int i = idx & 63;
    double freq_d = pow(1.0e6, -(double)(2 * i) / 128.0);
    float  ang = (float)s * (float)freq_d;
    double cd, sd;
    sincos((double)ang, &sd, &cd);
    cosT[idx] = (float)cd;
    sinT[idx] = (float)sd;
}

// ---------------------------------------------------------------------------
// Fused: (a) RMSNorm + RoPE + split for q/k rows (blocks < NORM_BLKS, one warp
// per row), (b) V transpose+split via smem tiles (remaining blocks).
// ---------------------------------------------------------------------------
#define NORM_BLKS (S * (HQ + G) / 8)          // 10240
#define VT_BLKS   ((S / 32) * ((G * HD) / 32)) // 2048

__global__ void norm_vsplit_kernel(const float* __restrict__ qkv,
                                   const float* __restrict__ qw,
                                   const float* __restrict__ kw,
                                   const float* __restrict__ cosT,
                                   const float* __restrict__ sinT,
                                   bf16* __restrict__ qh, bf16* __restrict__ ql,
                                   bf16* __restrict__ kh, bf16* __restrict__ kl,
                                   bf16* __restrict__ vth, bf16* __restrict__ vtl) {
    if (blockIdx.x < NORM_BLKS) {
        int gwarp = blockIdx.x * 8 + (threadIdx.x >> 5);
        int lane  = threadIdx.x & 31;
        int s  = gwarp / (HQ + G);
        int hh = gwarp % (HQ + G);

        const float* row;
        const float* w;
        bf16 *dh, *dl;
        if (hh < HQ) {
            row = qkv + (long long)s * E + hh * HD;            w = qw;
            dh = qh + (long long)s * D + hh * HD;
            dl = ql + (long long)s * D + hh * HD;
        } else {
            row = qkv + (long long)s * E + D + (hh - HQ) * HD; w = kw;
            dh = kh + (long long)s * (G * HD) + (hh - HQ) * HD;
            dl = kl + (long long)s * (G * HD) + (hh - HQ) * HD;
        }

        const float2* row2 = (const float2*)row;
        float2 a = row2[lane], b = row2[lane + 32];
        float ss = a.x * a.x + a.y * a.y + b.x * b.x + b.y * b.y;
        #pragma unroll
        for (int o = 16; o; o >>= 1) ss += __shfl_xor_sync(0xFFFFFFFFu, ss, o);
        float r = rsqrtf(ss * (1.0f / 128.0f) + EPSF);

        const float2* w2 = (const float2*)w;
        float2 wa = w2[lane], wb = w2[lane + 32];
        float ax = (a.x * r) * wa.x, ay = (a.y * r) * wa.y;
        float bx = (b.x * r) * wb.x, by = (b.y * r) * wb.y;

        int base = s * (HD / 2);
        float c0 = cosT[base + lane],      s0 = sinT[base + lane];
        float c1 = cosT[base + lane + 32], s1 = sinT[base + lane + 32];

        float o0 = ax * c0 - ay * s0, o1 = ax * s0 + ay * c0;
        float o2 = bx * c1 - by * s1, o3 = bx * s1 + by * c1;

        bf16 h0, l0, h1, l1, h2, l2, h3, l3;
        split1(o0, h0, l0); split1(o1, h1, l1);
        split1(o2, h2, l2); split1(o3, h3, l3);
        ((bf162*)dh)[lane]      = bf162(h0, h1);
        ((bf162*)dl)[lane]      = bf162(l0, l1);
        ((bf162*)dh)[lane + 32] = bf162(h2, h3);
        ((bf162*)dl)[lane + 32] = bf162(l2, l3);
    } else {
        // V transpose + split: vt[c][t]
        __shared__ float tile[32][33];
        int id = blockIdx.x - NORM_BLKS;
        int tbase = (id & 63) * 32;
        int cbase = (id >> 6) * 32;
        int tx = threadIdx.x & 31, ty = threadIdx.x >> 5;   // 32 x 8
        #pragma unroll
        for (int j = 0; j < 4; j++) {
            int row = ty + j * 8;
            tile[row][tx] = qkv[(long long)(tbase + row) * E + D + G * HD + cbase + tx];
        }
        __syncthreads();
        #pragma unroll
        for (int j = 0; j < 4; j++) {
            int c = cbase + ty + j * 8;
            float v = tile[tx][ty + j * 8];
            bf16 h, l;
            split1(v, h, l);
            long long o = (long long)c * S + tbase + tx;
            vth[o] = h; vtl[o] = l;
        }
    }
}

// ---------------------------------------------------------------------------
// Launch
// ---------------------------------------------------------------------------
extern "C" void kernel_launch(void* const* d_in, const int* in_sizes, int n_in,
                              void* d_out, int out_size) {
    const float* x     = (const float*)d_in[0];
    const float* w_qkv = (const float*)d_in[1];
    const float* w_out = (const float*)d_in[2];
    const float* qw    = (const float*)d_in[3];
    const float* kw    = (const float*)d_in[4];
    float* out = (float*)d_out;

    float *qkv, *cosT, *sinT;
    cudaGetSymbolAddress((void**)&qkv,  g_qkv);
    cudaGetSymbolAddress((void**)&cosT, g_cos);
    cudaGetSymbolAddress((void**)&sinT, g_sin);
    bf16 *xh,*xl,*wqh,*wql,*woh,*wol,*qh,*ql,*kh,*kl,*vth,*vtl,*ah,*al;
    cudaGetSymbolAddress((void**)&xh,  g_xh);  cudaGetSymbolAddress((void**)&xl,  g_xl);
    cudaGetSymbolAddress((void**)&wqh, g_wqh); cudaGetSymbolAddress((void**)&wql, g_wql);
    cudaGetSymbolAddress((void**)&woh, g_woh); cudaGetSymbolAddress((void**)&wol, g_wol);
    cudaGetSymbolAddress((void**)&qh,  g_qh);  cudaGetSymbolAddress((void**)&ql,  g_ql);
    cudaGetSymbolAddress((void**)&kh,  g_kh);  cudaGetSymbolAddress((void**)&kl,  g_kl);
    cudaGetSymbolAddress((void**)&vth, g_vth); cudaGetSymbolAddress((void**)&vtl, g_vtl);
    cudaGetSymbolAddress((void**)&ah,  g_ah);  cudaGetSymbolAddress((void**)&al,  g_al);

    const int SMEM = NSTG * STAGE_B;   // 81920
    cudaFuncSetAttribute(mma_gemm, cudaFuncAttributeMaxDynamicSharedMemorySize, SMEM);
    cudaFuncSetAttribute(flash_kernel, cudaFuncAttributeMaxDynamicSharedMemorySize, FSMEM);

    // #0 RoPE tables
    rope_table_kernel<<<(S * (HD / 2) + 255) / 256, 256>>>(cosT, sinT);

    // #1, #2: splits for QKV GEMM inputs
    {
        long long tx = (long long)S * D;
        split_kernel<<<(unsigned)((tx / 4 + 255) / 256), 256>>>(x, D, D, xh, xl, tx);
        long long tw = (long long)E * D;
        split_kernel<<<(unsigned)((tw / 4 + 255) / 256), 256>>>(w_qkv, D, D, wqh, wql, tw);
    }

    // #3 QKV projection: qkv = x @ w_qkv^T
    {
        dim3 grid(E / 128, S / 128, 1);
        mma_gemm<<<grid, 256, SMEM>>>(xh, xl, wqh, wql, qkv, D, D, D, E);
    }

    // #4 RMSNorm+RoPE+split (q/k) and V transpose+split, fused
    norm_vsplit_kernel<<<NORM_BLKS + VT_BLKS, 256>>>(qkv, qw, kw, cosT, sinT,
                                                     qh, ql, kh, kl, vth, vtl);

    // #5 fused flash attention -> ah/al   [ncu target]
    {
        dim3 grid(S / 128, HQ);
        flash_kernel<<<grid, 256, FSMEM>>>(qh, ql, kh, kl, vth, vtl, ah, al);
    }

    // #6 split w_out
    {
        long long to = (long long)D * D;
        split_kernel<<<(unsigned)((to / 4 + 255) / 256), 256>>>(w_out, D, D, woh, wol, to);
    }

    // #7 out = attn @ w_out^T
    {
        dim3 grid(D / 128, S / 128, 1);
        mma_gemm<<<grid, 256, SMEM>>>(ah, al, woh, wol, out, D, D, D, D);
    }
}